// round 14
// baseline (speedup 1.0000x reference)
#include <cuda_runtime.h>
#include <math.h>

#define BATCH 32
#define HEADS 32
#define DIM   128
#define KVLEN 1024
#define HID   4096
#define NQKV  12288
#define ROTD  64
#define QKV_SPLITS 16     // chunk 256
#define OPJ_SPLITS 64     // chunk 64
#define XPAD  36          // padded float row stride for xs transpose
#define KVSPLIT 2
#define KVHALF (KVLEN / KVSPLIT)   // 512

__device__ float g_qkv[BATCH * NQKV];                    // 1.5 MB
__device__ float g_attn[BATCH * HID];                    // 0.5 MB
__device__ float g_part[32 * BATCH * NQKV];              // 50 MB
__device__ float g_po[KVSPLIT * BATCH * HEADS * DIM];    // 1 MB partial outputs
__device__ float g_pm[KVSPLIT * BATCH * HEADS];          // partial maxes
__device__ float g_pl[KVSPLIT * BATCH * HEADS];          // partial expsums

// ---------- packed f32x2 helpers (FFMA2) ----------
__device__ __forceinline__ unsigned long long pk2(float a, float b) {
    return ((unsigned long long)__float_as_uint(b) << 32) |
            (unsigned long long)__float_as_uint(a);
}
__device__ __forceinline__ void fma2(unsigned long long &d,
                                     unsigned long long a,
                                     unsigned long long b) {
    asm("fma.rn.f32x2 %0, %1, %2, %0;" : "+l"(d) : "l"(a), "l"(b));
}
__device__ __forceinline__ float lo2(unsigned long long v) {
    return __uint_as_float((unsigned)v);
}
__device__ __forceinline__ float hi2(unsigned long long v) {
    return __uint_as_float((unsigned)(v >> 32));
}

// one k-step: 16 FFMA2 against one W row (4 cols) and 8 x values (R11 form)
__device__ __forceinline__ void gemm_step(unsigned long long acc[16],
                                          const float* xr, float4 w4) {
    unsigned long long x01 = *(const unsigned long long*)(xr);
    unsigned long long x23 = *(const unsigned long long*)(xr + 2);
    unsigned long long x45 = *(const unsigned long long*)(xr + 4);
    unsigned long long x67 = *(const unsigned long long*)(xr + 6);
    unsigned long long w0 = pk2(w4.x, w4.x);
    unsigned long long w1 = pk2(w4.y, w4.y);
    unsigned long long w2 = pk2(w4.z, w4.z);
    unsigned long long w3 = pk2(w4.w, w4.w);
    fma2(acc[0],  x01, w0); fma2(acc[1],  x23, w0);
    fma2(acc[2],  x45, w0); fma2(acc[3],  x67, w0);
    fma2(acc[4],  x01, w1); fma2(acc[5],  x23, w1);
    fma2(acc[6],  x45, w1); fma2(acc[7],  x67, w1);
    fma2(acc[8],  x01, w2); fma2(acc[9],  x23, w2);
    fma2(acc[10], x45, w2); fma2(acc[11], x67, w2);
    fma2(acc[12], x01, w3); fma2(acc[13], x23, w3);
    fma2(acc[14], x45, w3); fma2(acc[15], x67, w3);
}

// ---------- split-K GEMM (R11 core, CHUNK templated) ----------
template <int CHUNK>
__global__ void __launch_bounds__(256, 2)
gemm_splitk(const float* __restrict__ X, const float* __restrict__ W,
            float* __restrict__ part, int N, int K) {
    __shared__ float xs[CHUNK * XPAD];
    const int tcol = threadIdx.x & 63;
    const int bg   = threadIdx.x >> 6;                 // 0..3
    const int j    = blockIdx.x * 256 + tcol * 4;
    const int k0   = blockIdx.y * CHUNK;
    constexpr int CSH = (CHUNK == 256) ? 8 : (CHUNK == 128) ? 7 : 6;

    for (int i = threadIdx.x; i < BATCH * CHUNK; i += 256) {
        int b  = i >> CSH;           // i / CHUNK
        int kk = i & (CHUNK - 1);
        xs[kk * XPAD + b] = X[b * K + k0 + kk];
    }

    const float* wp = W + (size_t)k0 * N + j;
    float4 wA[8], wB[8];
#pragma unroll
    for (int u = 0; u < 8; u++)
        wA[u] = __ldcs((const float4*)(wp + (size_t)u * N));

    __syncthreads();

    unsigned long long acc[16];
#pragma unroll
    for (int i = 0; i < 16; i++) acc[i] = 0ull;

    const float* xp = xs + bg * 8;

#pragma unroll
    for (int kk16 = 0; kk16 < CHUNK; kk16 += 16) {
#pragma unroll
        for (int u = 0; u < 8; u++)
            wB[u] = __ldcs((const float4*)(wp + (size_t)(kk16 + 8 + u) * N));
#pragma unroll
        for (int u = 0; u < 8; u++)
            gemm_step(acc, xp + (kk16 + u) * XPAD, wA[u]);
        int nk = (kk16 + 16 < CHUNK) ? kk16 + 16 : 0;
#pragma unroll
        for (int u = 0; u < 8; u++)
            wA[u] = __ldcs((const float4*)(wp + (size_t)(nk + u) * N));
#pragma unroll
        for (int u = 0; u < 8; u++)
            gemm_step(acc, xp + (kk16 + 8 + u) * XPAD, wB[u]);
    }

    float* pb = part + (size_t)blockIdx.y * BATCH * N + j;
#pragma unroll
    for (int p = 0; p < 4; p++) {
        int b0 = bg * 8 + 2 * p;
        float4 v0 = make_float4(lo2(acc[p]), lo2(acc[4 + p]),
                                lo2(acc[8 + p]), lo2(acc[12 + p]));
        float4 v1 = make_float4(hi2(acc[p]), hi2(acc[4 + p]),
                                hi2(acc[8 + p]), hi2(acc[12 + p]));
        *(float4*)(pb + (size_t)b0 * N)       = v0;
        *(float4*)(pb + (size_t)(b0 + 1) * N) = v1;
    }
}

// ---------- split-K reduce for QKV, fused with RoPE ----------
#define ROPE_THREADS (BATCH * 2 * HEADS * ROTD)        // 131072
#define RR_TOTAL     (ROPE_THREADS + BATCH * HID)      // 262144
__global__ void reduce_rope(const float* __restrict__ part,
                            float* __restrict__ out,
                            const float* __restrict__ cosb,
                            const float* __restrict__ sinb) {
    int tid = blockIdx.x * 256 + threadIdx.x;
    if (tid < ROPE_THREADS) {
        int r = tid & (ROTD - 1);
        int h = (tid >> 6) & (HEADS - 1);
        int t = (tid >> 11) & 1;
        int b = tid >> 12;
        int col = t * HID + h * DIM + r;
        size_t i1 = (size_t)b * NQKV + col;
        size_t i2 = i1 + ROTD;
        float s1 = 0.f, s2 = 0.f;
#pragma unroll
        for (int sp = 0; sp < QKV_SPLITS; sp++) {
            size_t off = (size_t)sp * BATCH * NQKV;
            s1 += part[off + i1];
            s2 += part[off + i2];
        }
        float c = cosb[b * ROTD + r];
        float s = sinb[b * ROTD + r];
        out[i1] = s1 * c - s2 * s;
        out[i2] = s1 * s + s2 * c;
    } else {
        int v = tid - ROPE_THREADS;
        int c = v & (HID - 1);
        int b = v >> 12;
        size_t i = (size_t)b * NQKV + 2 * HID + c;
        float s = 0.f;
#pragma unroll
        for (int sp = 0; sp < QKV_SPLITS; sp++)
            s += part[(size_t)sp * BATCH * NQKV + i];
        out[i] = s;
    }
}

// ---------- plain deterministic split-K reduction (o-proj) ----------
__global__ void reduce_splitk(const float* __restrict__ part,
                              float* __restrict__ out, int N, int nsp) {
    int i = blockIdx.x * 256 + threadIdx.x;
    if (i >= BATCH * N) return;
    float s = 0.f;
#pragma unroll 8
    for (int sp = 0; sp < nsp; sp++) s += part[(size_t)sp * BATCH * N + i];
    out[i] = s;
}

// ---------- attention, flash-decode split: one block per (b,h,half) ----------
__global__ void __launch_bounds__(128)
attn_split(const float* __restrict__ cache, const int* __restrict__ idx) {
    const int bh2 = blockIdx.x;
    const int half = bh2 & (KVSPLIT - 1);
    const int bh = bh2 >> 1;               // KVSPLIT == 2
    const int b = bh >> 5, h = bh & 31;
    const int tid = threadIdx.x;
    const int warp = tid >> 5, lane = tid & 31;

    __shared__ float sc[KVHALF];
    __shared__ float red[4 * DIM];
    __shared__ float wredA[4], wredB[4];

    const int p = idx[b] - b * KVLEN;
    const float scale = 0.08838834764831845f;   // 1/sqrt(128)
    const int s0 = half * KVHALF;

    const float* qp  = g_qkv + (size_t)b * NQKV + h * DIM;
    const float4 q4  = ((const float4*)qp)[lane];
    const float4 kn4 = ((const float4*)(qp + HID))[lane];

    const size_t rowstride = 2 * HEADS * DIM;
    const float* kbase = cache + (size_t)b * KVLEN * rowstride + h * DIM;

    // ---- pass 1: scores for rows [s0, s0+512), 4 rows per warp-iter ----
    for (int s = s0 + warp; s < s0 + KVHALF; s += 16) {
        int s1 = s + 4, s2 = s + 8, s3 = s + 12;
        float4 k0 = __ldcs((const float4*)(kbase + (size_t)s  * rowstride) + lane);
        float4 k1 = __ldcs((const float4*)(kbase + (size_t)s1 * rowstride) + lane);
        float4 k2 = __ldcs((const float4*)(kbase + (size_t)s2 * rowstride) + lane);
        float4 k3 = __ldcs((const float4*)(kbase + (size_t)s3 * rowstride) + lane);
        if (s  == p) k0 = kn4;
        if (s1 == p) k1 = kn4;
        if (s2 == p) k2 = kn4;
        if (s3 == p) k3 = kn4;
        float d0 = q4.x*k0.x + q4.y*k0.y + q4.z*k0.z + q4.w*k0.w;
        float d1 = q4.x*k1.x + q4.y*k1.y + q4.z*k1.z + q4.w*k1.w;
        float d2 = q4.x*k2.x + q4.y*k2.y + q4.z*k2.z + q4.w*k2.w;
        float d3 = q4.x*k3.x + q4.y*k3.y + q4.z*k3.z + q4.w*k3.w;
#pragma unroll
        for (int o = 16; o > 0; o >>= 1) {
            d0 += __shfl_xor_sync(0xffffffffu, d0, o);
            d1 += __shfl_xor_sync(0xffffffffu, d1, o);
            d2 += __shfl_xor_sync(0xffffffffu, d2, o);
            d3 += __shfl_xor_sync(0xffffffffu, d3, o);
        }
        if (lane == 0) {
            sc[s  - s0] = d0 * scale; sc[s1 - s0] = d1 * scale;
            sc[s2 - s0] = d2 * scale; sc[s3 - s0] = d3 * scale;
        }
    }
    __syncthreads();

    // ---- local softmax (unnormalized) ----
    float m = -3.4e38f;
#pragma unroll
    for (int i = tid; i < KVHALF; i += 128) m = fmaxf(m, sc[i]);
#pragma unroll
    for (int o = 16; o > 0; o >>= 1)
        m = fmaxf(m, __shfl_xor_sync(0xffffffffu, m, o));
    if (lane == 0) wredA[warp] = m;
    __syncthreads();
    float bm = fmaxf(fmaxf(wredA[0], wredA[1]), fmaxf(wredA[2], wredA[3]));

    float ssum = 0.f;
#pragma unroll
    for (int i = tid; i < KVHALF; i += 128) {
        float e = __expf(sc[i] - bm);
        sc[i] = e;
        ssum += e;
    }
#pragma unroll
    for (int o = 16; o > 0; o >>= 1)
        ssum += __shfl_xor_sync(0xffffffffu, ssum, o);
    if (lane == 0) wredB[warp] = ssum;
    __syncthreads();
    const float lsum = wredB[0] + wredB[1] + wredB[2] + wredB[3];

    // ---- pass 2: unnormalized P @ V over rows [s0, s0+512) ----
    const float* vbase = kbase + HEADS * DIM;
    const float4 vn4 = ((const float4*)(qp + 2 * HID))[lane];
    float4 acc = make_float4(0.f, 0.f, 0.f, 0.f);
    for (int s = s0 + warp; s < s0 + KVHALF; s += 16) {
        int s1 = s + 4, s2 = s + 8, s3 = s + 12;
        float4 v0 = __ldcs((const float4*)(vbase + (size_t)s  * rowstride) + lane);
        float4 v1 = __ldcs((const float4*)(vbase + (size_t)s1 * rowstride) + lane);
        float4 v2 = __ldcs((const float4*)(vbase + (size_t)s2 * rowstride) + lane);
        float4 v3 = __ldcs((const float4*)(vbase + (size_t)s3 * rowstride) + lane);
        if (s  == p) v0 = vn4;
        if (s1 == p) v1 = vn4;
        if (s2 == p) v2 = vn4;
        if (s3 == p) v3 = vn4;
        float p0 = sc[s - s0], p1 = sc[s1 - s0], p2 = sc[s2 - s0], p3 = sc[s3 - s0];
        acc.x += p0*v0.x + p1*v1.x + p2*v2.x + p3*v3.x;
        acc.y += p0*v0.y + p1*v1.y + p2*v2.y + p3*v3.y;
        acc.z += p0*v0.z + p1*v1.z + p2*v2.z + p3*v3.z;
        acc.w += p0*v0.w + p1*v1.w + p2*v2.w + p3*v3.w;
    }
    ((float4*)(red + warp * DIM))[lane] = acc;
    __syncthreads();

    if (tid < DIM) {
        float o = red[tid] + red[DIM + tid] + red[2 * DIM + tid] + red[3 * DIM + tid];
        g_po[((size_t)half * BATCH * HEADS + bh) * DIM + tid] = o;
    }
    if (tid == 0) {
        g_pm[half * BATCH * HEADS + bh] = bm;
        g_pl[half * BATCH * HEADS + bh] = lsum;
    }
}

// ---------- combine the KVSPLIT partials ----------
__global__ void attn_combine() {
    int i = blockIdx.x * 256 + threadIdx.x;     // 0 .. BATCH*HEADS*DIM-1
    int bh = i >> 7;
    int d  = i & (DIM - 1);
    float m0 = g_pm[bh], m1 = g_pm[BATCH * HEADS + bh];
    float l0 = g_pl[bh], l1 = g_pl[BATCH * HEADS + bh];
    float M  = fmaxf(m0, m1);
    float e0 = __expf(m0 - M), e1 = __expf(m1 - M);
    float o0 = g_po[(size_t)bh * DIM + d];
    float o1 = g_po[(size_t)(BATCH * HEADS + bh) * DIM + d];
    float o  = (o0 * e0 + o1 * e1) / (l0 * e0 + l1 * e1);
    int b = bh >> 5, h = bh & 31;
    g_attn[(size_t)b * HID + h * DIM + d] = o;
}

extern "C" void kernel_launch(void* const* d_in, const int* in_sizes, int n_in,
                              void* d_out, int out_size) {
    const float* hidden = (const float*)d_in[0];
    const float* cosb   = (const float*)d_in[1];
    const float* sinb   = (const float*)d_in[2];
    const float* cache  = (const float*)d_in[3];
    const int*   idx    = (const int*)d_in[4];
    const float* w_qkv  = (const float*)d_in[5];
    const float* w_o    = (const float*)d_in[6];
    float* out = (float*)d_out;

    float *qkv_p, *attn_p, *part_p;
    cudaGetSymbolAddress((void**)&qkv_p,  g_qkv);
    cudaGetSymbolAddress((void**)&attn_p, g_attn);
    cudaGetSymbolAddress((void**)&part_p, g_part);

    // 1) QKV projection: 16 splits x chunk 256 + fused reduce+RoPE
    gemm_splitk<256><<<dim3(NQKV / 256, QKV_SPLITS), 256>>>(hidden, w_qkv, part_p, NQKV, HID);
    reduce_rope<<<RR_TOTAL / 256, 256>>>(part_p, qkv_p, cosb, sinb);
    // 2) attention: flash-decode split over KV halves + combine
    attn_split<<<BATCH * HEADS * KVSPLIT, 128>>>(cache, idx);
    attn_combine<<<(BATCH * HID) / 256, 256>>>();
    // 3) output projection: 64 splits x chunk 64 + reduce
    gemm_splitk<64><<<dim3(HID / 256, OPJ_SPLITS), 256>>>(attn_p, w_o, part_p, HID, HID);
    reduce_splitk<<<(BATCH * HID + 255) / 256, 256>>>(part_p, out, HID, OPJ_SPLITS);
}

// round 15
// speedup vs baseline: 1.1455x; 1.1455x over previous
#include <cuda_runtime.h>
#include <math.h>

#define BATCH 32
#define HEADS 32
#define DIM   128
#define KVLEN 1024
#define HID   4096
#define NQKV  12288
#define ROTD  64
#define QKV_SPLITS 16     // chunk 256
#define OPJ_SPLITS 64     // chunk 64
#define XPAD  36          // padded float row stride for xs transpose

__device__ float g_qkv[BATCH * NQKV];                    // 1.5 MB
__device__ float g_attn[BATCH * HID];                    // 0.5 MB
__device__ float g_part[32 * BATCH * NQKV];              // 50 MB

// ---------- packed f32x2 helpers (FFMA2) ----------
__device__ __forceinline__ unsigned long long pk2(float a, float b) {
    return ((unsigned long long)__float_as_uint(b) << 32) |
            (unsigned long long)__float_as_uint(a);
}
__device__ __forceinline__ void fma2(unsigned long long &d,
                                     unsigned long long a,
                                     unsigned long long b) {
    asm("fma.rn.f32x2 %0, %1, %2, %0;" : "+l"(d) : "l"(a), "l"(b));
}
__device__ __forceinline__ float lo2(unsigned long long v) {
    return __uint_as_float((unsigned)v);
}
__device__ __forceinline__ float hi2(unsigned long long v) {
    return __uint_as_float((unsigned)(v >> 32));
}

// one k-step: 16 FFMA2 against one W row (4 cols) and 8 x values (R11 form)
__device__ __forceinline__ void gemm_step(unsigned long long acc[16],
                                          const float* xr, float4 w4) {
    unsigned long long x01 = *(const unsigned long long*)(xr);
    unsigned long long x23 = *(const unsigned long long*)(xr + 2);
    unsigned long long x45 = *(const unsigned long long*)(xr + 4);
    unsigned long long x67 = *(const unsigned long long*)(xr + 6);
    unsigned long long w0 = pk2(w4.x, w4.x);
    unsigned long long w1 = pk2(w4.y, w4.y);
    unsigned long long w2 = pk2(w4.z, w4.z);
    unsigned long long w3 = pk2(w4.w, w4.w);
    fma2(acc[0],  x01, w0); fma2(acc[1],  x23, w0);
    fma2(acc[2],  x45, w0); fma2(acc[3],  x67, w0);
    fma2(acc[4],  x01, w1); fma2(acc[5],  x23, w1);
    fma2(acc[6],  x45, w1); fma2(acc[7],  x67, w1);
    fma2(acc[8],  x01, w2); fma2(acc[9],  x23, w2);
    fma2(acc[10], x45, w2); fma2(acc[11], x67, w2);
    fma2(acc[12], x01, w3); fma2(acc[13], x23, w3);
    fma2(acc[14], x45, w3); fma2(acc[15], x67, w3);
}

// ---------- split-K GEMM (R11 core, CHUNK templated) ----------
template <int CHUNK>
__global__ void __launch_bounds__(256, 2)
gemm_splitk(const float* __restrict__ X, const float* __restrict__ W,
            float* __restrict__ part, int N, int K) {
    __shared__ float xs[CHUNK * XPAD];
    const int tcol = threadIdx.x & 63;
    const int bg   = threadIdx.x >> 6;                 // 0..3
    const int j    = blockIdx.x * 256 + tcol * 4;
    const int k0   = blockIdx.y * CHUNK;
    constexpr int CSH = (CHUNK == 256) ? 8 : (CHUNK == 128) ? 7 : 6;

    for (int i = threadIdx.x; i < BATCH * CHUNK; i += 256) {
        int b  = i >> CSH;           // i / CHUNK
        int kk = i & (CHUNK - 1);
        xs[kk * XPAD + b] = X[b * K + k0 + kk];
    }

    const float* wp = W + (size_t)k0 * N + j;
    float4 wA[8], wB[8];
#pragma unroll
    for (int u = 0; u < 8; u++)
        wA[u] = __ldcs((const float4*)(wp + (size_t)u * N));

    __syncthreads();

    unsigned long long acc[16];
#pragma unroll
    for (int i = 0; i < 16; i++) acc[i] = 0ull;

    const float* xp = xs + bg * 8;

#pragma unroll
    for (int kk16 = 0; kk16 < CHUNK; kk16 += 16) {
#pragma unroll
        for (int u = 0; u < 8; u++)
            wB[u] = __ldcs((const float4*)(wp + (size_t)(kk16 + 8 + u) * N));
#pragma unroll
        for (int u = 0; u < 8; u++)
            gemm_step(acc, xp + (kk16 + u) * XPAD, wA[u]);
        int nk = (kk16 + 16 < CHUNK) ? kk16 + 16 : 0;
#pragma unroll
        for (int u = 0; u < 8; u++)
            wA[u] = __ldcs((const float4*)(wp + (size_t)(nk + u) * N));
#pragma unroll
        for (int u = 0; u < 8; u++)
            gemm_step(acc, xp + (kk16 + 8 + u) * XPAD, wB[u]);
    }

    float* pb = part + (size_t)blockIdx.y * BATCH * N + j;
#pragma unroll
    for (int p = 0; p < 4; p++) {
        int b0 = bg * 8 + 2 * p;
        float4 v0 = make_float4(lo2(acc[p]), lo2(acc[4 + p]),
                                lo2(acc[8 + p]), lo2(acc[12 + p]));
        float4 v1 = make_float4(hi2(acc[p]), hi2(acc[4 + p]),
                                hi2(acc[8 + p]), hi2(acc[12 + p]));
        *(float4*)(pb + (size_t)b0 * N)       = v0;
        *(float4*)(pb + (size_t)(b0 + 1) * N) = v1;
    }
}

// ---------- split-K reduce for QKV, fused with RoPE ----------
#define ROPE_THREADS (BATCH * 2 * HEADS * ROTD)        // 131072
#define RR_TOTAL     (ROPE_THREADS + BATCH * HID)      // 262144
__global__ void reduce_rope(const float* __restrict__ part,
                            float* __restrict__ out,
                            const float* __restrict__ cosb,
                            const float* __restrict__ sinb) {
    int tid = blockIdx.x * 256 + threadIdx.x;
    if (tid < ROPE_THREADS) {
        int r = tid & (ROTD - 1);
        int h = (tid >> 6) & (HEADS - 1);
        int t = (tid >> 11) & 1;
        int b = tid >> 12;
        int col = t * HID + h * DIM + r;
        size_t i1 = (size_t)b * NQKV + col;
        size_t i2 = i1 + ROTD;
        float s1 = 0.f, s2 = 0.f;
#pragma unroll
        for (int sp = 0; sp < QKV_SPLITS; sp++) {
            size_t off = (size_t)sp * BATCH * NQKV;
            s1 += part[off + i1];
            s2 += part[off + i2];
        }
        float c = cosb[b * ROTD + r];
        float s = sinb[b * ROTD + r];
        out[i1] = s1 * c - s2 * s;
        out[i2] = s1 * s + s2 * c;
    } else {
        int v = tid - ROPE_THREADS;
        int c = v & (HID - 1);
        int b = v >> 12;
        size_t i = (size_t)b * NQKV + 2 * HID + c;
        float s = 0.f;
#pragma unroll
        for (int sp = 0; sp < QKV_SPLITS; sp++)
            s += part[(size_t)sp * BATCH * NQKV + i];
        out[i] = s;
    }
}

// ---------- plain deterministic split-K reduction (o-proj) ----------
__global__ void reduce_splitk(const float* __restrict__ part,
                              float* __restrict__ out, int N, int nsp) {
    int i = blockIdx.x * 256 + threadIdx.x;
    if (i >= BATCH * N) return;
    float s = 0.f;
#pragma unroll 8
    for (int sp = 0; sp < nsp; sp++) s += part[(size_t)sp * BATCH * N + i];
    out[i] = s;
}

// ---------- attention: one 128-thread block per (b,h), pipelined loads ----------
__global__ void __launch_bounds__(128)
attn_kernel(const float* __restrict__ cache, const int* __restrict__ idx) {
    const int bh = blockIdx.x;
    const int b = bh >> 5, h = bh & 31;
    const int tid = threadIdx.x;
    const int warp = tid >> 5, lane = tid & 31;

    __shared__ float sc[KVLEN];
    __shared__ float red[4 * DIM];
    __shared__ float wredA[4], wredB[4];

    const int p = idx[b] - b * KVLEN;
    const float scale = 0.08838834764831845f;   // 1/sqrt(128)

    const float* qp  = g_qkv + (size_t)b * NQKV + h * DIM;
    const float4 q4  = ((const float4*)qp)[lane];
    const float4 kn4 = ((const float4*)(qp + HID))[lane];

    const size_t rowstride = 2 * HEADS * DIM;
    const float* kbase = cache + (size_t)b * KVLEN * rowstride + h * DIM;

    // ---- pass 1: scores, 4 rows per warp-iter, next iter's loads prefetched ----
    {
        float4 k0 = __ldcs((const float4*)(kbase + (size_t)(warp)      * rowstride) + lane);
        float4 k1 = __ldcs((const float4*)(kbase + (size_t)(warp + 4)  * rowstride) + lane);
        float4 k2 = __ldcs((const float4*)(kbase + (size_t)(warp + 8)  * rowstride) + lane);
        float4 k3 = __ldcs((const float4*)(kbase + (size_t)(warp + 12) * rowstride) + lane);
        for (int s = warp; s < KVLEN; s += 16) {
            // prefetch next iteration before the shuffle chain
            float4 n0, n1, n2, n3;
            int sn = s + 16;
            if (sn < KVLEN) {
                n0 = __ldcs((const float4*)(kbase + (size_t)sn        * rowstride) + lane);
                n1 = __ldcs((const float4*)(kbase + (size_t)(sn + 4)  * rowstride) + lane);
                n2 = __ldcs((const float4*)(kbase + (size_t)(sn + 8)  * rowstride) + lane);
                n3 = __ldcs((const float4*)(kbase + (size_t)(sn + 12) * rowstride) + lane);
            }
            if (s      == p) k0 = kn4;
            if (s + 4  == p) k1 = kn4;
            if (s + 8  == p) k2 = kn4;
            if (s + 12 == p) k3 = kn4;
            float d0 = q4.x*k0.x + q4.y*k0.y + q4.z*k0.z + q4.w*k0.w;
            float d1 = q4.x*k1.x + q4.y*k1.y + q4.z*k1.z + q4.w*k1.w;
            float d2 = q4.x*k2.x + q4.y*k2.y + q4.z*k2.z + q4.w*k2.w;
            float d3 = q4.x*k3.x + q4.y*k3.y + q4.z*k3.z + q4.w*k3.w;
#pragma unroll
            for (int o = 16; o > 0; o >>= 1) {
                d0 += __shfl_xor_sync(0xffffffffu, d0, o);
                d1 += __shfl_xor_sync(0xffffffffu, d1, o);
                d2 += __shfl_xor_sync(0xffffffffu, d2, o);
                d3 += __shfl_xor_sync(0xffffffffu, d3, o);
            }
            if (lane == 0) {
                sc[s]      = d0 * scale; sc[s + 4]  = d1 * scale;
                sc[s + 8]  = d2 * scale; sc[s + 12] = d3 * scale;
            }
            k0 = n0; k1 = n1; k2 = n2; k3 = n3;
        }
    }
    __syncthreads();

    // ---- softmax ----
    float m = -3.4e38f;
#pragma unroll
    for (int i = tid; i < KVLEN; i += 128) m = fmaxf(m, sc[i]);
#pragma unroll
    for (int o = 16; o > 0; o >>= 1)
        m = fmaxf(m, __shfl_xor_sync(0xffffffffu, m, o));
    if (lane == 0) wredA[warp] = m;
    __syncthreads();
    float bm = fmaxf(fmaxf(wredA[0], wredA[1]), fmaxf(wredA[2], wredA[3]));

    float ssum = 0.f;
#pragma unroll
    for (int i = tid; i < KVLEN; i += 128) {
        float e = __expf(sc[i] - bm);
        sc[i] = e;
        ssum += e;
    }
#pragma unroll
    for (int o = 16; o > 0; o >>= 1)
        ssum += __shfl_xor_sync(0xffffffffu, ssum, o);
    if (lane == 0) wredB[warp] = ssum;
    __syncthreads();
    const float inv = 1.0f / (wredB[0] + wredB[1] + wredB[2] + wredB[3]);

    // ---- pass 2: P @ V, 4 rows per warp-iter, pipelined loads ----
    const float* vbase = kbase + HEADS * DIM;
    const float4 vn4 = ((const float4*)(qp + 2 * HID))[lane];
    float4 acc = make_float4(0.f, 0.f, 0.f, 0.f);
    {
        float4 v0 = __ldcs((const float4*)(vbase + (size_t)(warp)      * rowstride) + lane);
        float4 v1 = __ldcs((const float4*)(vbase + (size_t)(warp + 4)  * rowstride) + lane);
        float4 v2 = __ldcs((const float4*)(vbase + (size_t)(warp + 8)  * rowstride) + lane);
        float4 v3 = __ldcs((const float4*)(vbase + (size_t)(warp + 12) * rowstride) + lane);
        for (int s = warp; s < KVLEN; s += 16) {
            float4 n0, n1, n2, n3;
            int sn = s + 16;
            if (sn < KVLEN) {
                n0 = __ldcs((const float4*)(vbase + (size_t)sn        * rowstride) + lane);
                n1 = __ldcs((const float4*)(vbase + (size_t)(sn + 4)  * rowstride) + lane);
                n2 = __ldcs((const float4*)(vbase + (size_t)(sn + 8)  * rowstride) + lane);
                n3 = __ldcs((const float4*)(vbase + (size_t)(sn + 12) * rowstride) + lane);
            }
            if (s      == p) v0 = vn4;
            if (s + 4  == p) v1 = vn4;
            if (s + 8  == p) v2 = vn4;
            if (s + 12 == p) v3 = vn4;
            float p0 = sc[s], p1 = sc[s + 4], p2 = sc[s + 8], p3 = sc[s + 12];
            acc.x += p0*v0.x + p1*v1.x + p2*v2.x + p3*v3.x;
            acc.y += p0*v0.y + p1*v1.y + p2*v2.y + p3*v3.y;
            acc.z += p0*v0.z + p1*v1.z + p2*v2.z + p3*v3.z;
            acc.w += p0*v0.w + p1*v1.w + p2*v2.w + p3*v3.w;
            v0 = n0; v1 = n1; v2 = n2; v3 = n3;
        }
    }
    ((float4*)(red + warp * DIM))[lane] = acc;
    __syncthreads();

    if (tid < DIM) {
        float o = red[tid] + red[DIM + tid] + red[2 * DIM + tid] + red[3 * DIM + tid];
        g_attn[(size_t)b * HID + h * DIM + tid] = o * inv;
    }
}

extern "C" void kernel_launch(void* const* d_in, const int* in_sizes, int n_in,
                              void* d_out, int out_size) {
    const float* hidden = (const float*)d_in[0];
    const float* cosb   = (const float*)d_in[1];
    const float* sinb   = (const float*)d_in[2];
    const float* cache  = (const float*)d_in[3];
    const int*   idx    = (const int*)d_in[4];
    const float* w_qkv  = (const float*)d_in[5];
    const float* w_o    = (const float*)d_in[6];
    float* out = (float*)d_out;

    float *qkv_p, *attn_p, *part_p;
    cudaGetSymbolAddress((void**)&qkv_p,  g_qkv);
    cudaGetSymbolAddress((void**)&attn_p, g_attn);
    cudaGetSymbolAddress((void**)&part_p, g_part);

    // 1) QKV projection: 16 splits x chunk 256 + fused reduce+RoPE
    gemm_splitk<256><<<dim3(NQKV / 256, QKV_SPLITS), 256>>>(hidden, w_qkv, part_p, NQKV, HID);
    reduce_rope<<<RR_TOTAL / 256, 256>>>(part_p, qkv_p, cosb, sinb);
    // 2) attention over kv cache (fresh k/v substituted in-register)
    attn_kernel<<<BATCH * HEADS, 128>>>(cache, idx);
    // 3) output projection: 64 splits x chunk 64 + reduce
    gemm_splitk<64><<<dim3(HID / 256, OPJ_SPLITS), 256>>>(attn_p, w_o, part_p, HID, HID);
    reduce_splitk<<<(BATCH * HID + 255) / 256, 256>>>(part_p, out, HID, OPJ_SPLITS);
}

// round 16
// speedup vs baseline: 1.1633x; 1.0156x over previous
#include <cuda_runtime.h>
#include <math.h>

#define BATCH 32
#define HEADS 32
#define DIM   128
#define KVLEN 1024
#define HID   4096
#define NQKV  12288
#define ROTD  64
#define QKV_SPLITS 16     // chunk 256
#define OPJ_SPLITS 64     // chunk 64
#define XPAD  36          // padded float row stride for xs transpose

__device__ float g_attn[BATCH * HID];                    // 0.5 MB
__device__ float g_part[32 * BATCH * NQKV];              // 50 MB

// ---------- packed f32x2 helpers (FFMA2) ----------
__device__ __forceinline__ unsigned long long pk2(float a, float b) {
    return ((unsigned long long)__float_as_uint(b) << 32) |
            (unsigned long long)__float_as_uint(a);
}
__device__ __forceinline__ void fma2(unsigned long long &d,
                                     unsigned long long a,
                                     unsigned long long b) {
    asm("fma.rn.f32x2 %0, %1, %2, %0;" : "+l"(d) : "l"(a), "l"(b));
}
__device__ __forceinline__ float lo2(unsigned long long v) {
    return __uint_as_float((unsigned)v);
}
__device__ __forceinline__ float hi2(unsigned long long v) {
    return __uint_as_float((unsigned)(v >> 32));
}

// one k-step: 16 FFMA2 against one W row (4 cols) and 8 x values (R11 form)
__device__ __forceinline__ void gemm_step(unsigned long long acc[16],
                                          const float* xr, float4 w4) {
    unsigned long long x01 = *(const unsigned long long*)(xr);
    unsigned long long x23 = *(const unsigned long long*)(xr + 2);
    unsigned long long x45 = *(const unsigned long long*)(xr + 4);
    unsigned long long x67 = *(const unsigned long long*)(xr + 6);
    unsigned long long w0 = pk2(w4.x, w4.x);
    unsigned long long w1 = pk2(w4.y, w4.y);
    unsigned long long w2 = pk2(w4.z, w4.z);
    unsigned long long w3 = pk2(w4.w, w4.w);
    fma2(acc[0],  x01, w0); fma2(acc[1],  x23, w0);
    fma2(acc[2],  x45, w0); fma2(acc[3],  x67, w0);
    fma2(acc[4],  x01, w1); fma2(acc[5],  x23, w1);
    fma2(acc[6],  x45, w1); fma2(acc[7],  x67, w1);
    fma2(acc[8],  x01, w2); fma2(acc[9],  x23, w2);
    fma2(acc[10], x45, w2); fma2(acc[11], x67, w2);
    fma2(acc[12], x01, w3); fma2(acc[13], x23, w3);
    fma2(acc[14], x45, w3); fma2(acc[15], x67, w3);
}

// ---------- split-K GEMM (R11 core, CHUNK templated) ----------
template <int CHUNK>
__global__ void __launch_bounds__(256, 2)
gemm_splitk(const float* __restrict__ X, const float* __restrict__ W,
            float* __restrict__ part, int N, int K) {
    __shared__ float xs[CHUNK * XPAD];
    const int tcol = threadIdx.x & 63;
    const int bg   = threadIdx.x >> 6;                 // 0..3
    const int j    = blockIdx.x * 256 + tcol * 4;
    const int k0   = blockIdx.y * CHUNK;
    constexpr int CSH = (CHUNK == 256) ? 8 : (CHUNK == 128) ? 7 : 6;

    for (int i = threadIdx.x; i < BATCH * CHUNK; i += 256) {
        int b  = i >> CSH;           // i / CHUNK
        int kk = i & (CHUNK - 1);
        xs[kk * XPAD + b] = X[b * K + k0 + kk];
    }

    const float* wp = W + (size_t)k0 * N + j;
    float4 wA[8], wB[8];
#pragma unroll
    for (int u = 0; u < 8; u++)
        wA[u] = __ldcs((const float4*)(wp + (size_t)u * N));

    __syncthreads();

    unsigned long long acc[16];
#pragma unroll
    for (int i = 0; i < 16; i++) acc[i] = 0ull;

    const float* xp = xs + bg * 8;

#pragma unroll
    for (int kk16 = 0; kk16 < CHUNK; kk16 += 16) {
#pragma unroll
        for (int u = 0; u < 8; u++)
            wB[u] = __ldcs((const float4*)(wp + (size_t)(kk16 + 8 + u) * N));
#pragma unroll
        for (int u = 0; u < 8; u++)
            gemm_step(acc, xp + (kk16 + u) * XPAD, wA[u]);
        int nk = (kk16 + 16 < CHUNK) ? kk16 + 16 : 0;
#pragma unroll
        for (int u = 0; u < 8; u++)
            wA[u] = __ldcs((const float4*)(wp + (size_t)(nk + u) * N));
#pragma unroll
        for (int u = 0; u < 8; u++)
            gemm_step(acc, xp + (kk16 + 8 + u) * XPAD, wB[u]);
    }

    float* pb = part + (size_t)blockIdx.y * BATCH * N + j;
#pragma unroll
    for (int p = 0; p < 4; p++) {
        int b0 = bg * 8 + 2 * p;
        float4 v0 = make_float4(lo2(acc[p]), lo2(acc[4 + p]),
                                lo2(acc[8 + p]), lo2(acc[12 + p]));
        float4 v1 = make_float4(hi2(acc[p]), hi2(acc[4 + p]),
                                hi2(acc[8 + p]), hi2(acc[12 + p]));
        *(float4*)(pb + (size_t)b0 * N)       = v0;
        *(float4*)(pb + (size_t)(b0 + 1) * N) = v1;
    }
}

// ---------- plain deterministic split-K reduction (o-proj) ----------
__global__ void reduce_splitk(const float* __restrict__ part,
                              float* __restrict__ out, int N, int nsp) {
    int i = blockIdx.x * 256 + threadIdx.x;
    if (i >= BATCH * N) return;
    float s = 0.f;
#pragma unroll 8
    for (int sp = 0; sp < nsp; sp++) s += part[(size_t)sp * BATCH * N + i];
    out[i] = s;
}

// ---------- attention with fused QKV split-reduce + RoPE prologue ----------
// one 128-thread block per (b,h); block (b,h) is the sole consumer of
// q/k/v[b,h], so it reduces its own 3x128 values over the 16 GEMM splits.
__global__ void __launch_bounds__(128)
attn_kernel(const float* __restrict__ part, const float* __restrict__ cache,
            const int* __restrict__ idx, const float* __restrict__ cosb,
            const float* __restrict__ sinb) {
    const int bh = blockIdx.x;
    const int b = bh >> 5, h = bh & 31;
    const int tid = threadIdx.x;
    const int warp = tid >> 5, lane = tid & 31;

    __shared__ float sc[KVLEN];
    __shared__ float red[4 * DIM];
    __shared__ float qs[DIM], ks[DIM], vs[DIM];
    __shared__ float wredA[4], wredB[4];

    const int p = idx[b] - b * KVLEN;
    const float scale = 0.08838834764831845f;   // 1/sqrt(128)

    // --- prologue: reduce q/k/v over splits (same order as before: sp asc) ---
    {
        const float* pp = part + (size_t)b * NQKV + h * DIM + tid;
        float sq = 0.f, sk = 0.f, sv = 0.f;
#pragma unroll
        for (int sp = 0; sp < QKV_SPLITS; sp++) {
            const float* base = pp + (size_t)sp * BATCH * NQKV;
            sq += __ldcs(base);
            sk += __ldcs(base + HID);
            sv += __ldcs(base + 2 * HID);
        }
        qs[tid] = sq; ks[tid] = sk; vs[tid] = sv;
    }
    __syncthreads();
    // --- RoPE on q, k (pairs r, r+64) ---
    if (tid < ROTD) {
        float c = cosb[b * ROTD + tid];
        float s = sinb[b * ROTD + tid];
        float q1 = qs[tid], q2 = qs[tid + ROTD];
        qs[tid] = q1 * c - q2 * s;
        qs[tid + ROTD] = q1 * s + q2 * c;
        float k1 = ks[tid], k2 = ks[tid + ROTD];
        ks[tid] = k1 * c - k2 * s;
        ks[tid + ROTD] = k1 * s + k2 * c;
    }
    __syncthreads();

    const float4 q4  = ((const float4*)qs)[lane];
    const float4 kn4 = ((const float4*)ks)[lane];

    const size_t rowstride = 2 * HEADS * DIM;
    const float* kbase = cache + (size_t)b * KVLEN * rowstride + h * DIM;

    // ---- pass 1: scores, 4 rows per warp-iter, next iter's loads prefetched ----
    {
        float4 k0 = __ldcs((const float4*)(kbase + (size_t)(warp)      * rowstride) + lane);
        float4 k1 = __ldcs((const float4*)(kbase + (size_t)(warp + 4)  * rowstride) + lane);
        float4 k2 = __ldcs((const float4*)(kbase + (size_t)(warp + 8)  * rowstride) + lane);
        float4 k3 = __ldcs((const float4*)(kbase + (size_t)(warp + 12) * rowstride) + lane);
        for (int s = warp; s < KVLEN; s += 16) {
            float4 n0, n1, n2, n3;
            int sn = s + 16;
            if (sn < KVLEN) {
                n0 = __ldcs((const float4*)(kbase + (size_t)sn        * rowstride) + lane);
                n1 = __ldcs((const float4*)(kbase + (size_t)(sn + 4)  * rowstride) + lane);
                n2 = __ldcs((const float4*)(kbase + (size_t)(sn + 8)  * rowstride) + lane);
                n3 = __ldcs((const float4*)(kbase + (size_t)(sn + 12) * rowstride) + lane);
            }
            if (s      == p) k0 = kn4;
            if (s + 4  == p) k1 = kn4;
            if (s + 8  == p) k2 = kn4;
            if (s + 12 == p) k3 = kn4;
            float d0 = q4.x*k0.x + q4.y*k0.y + q4.z*k0.z + q4.w*k0.w;
            float d1 = q4.x*k1.x + q4.y*k1.y + q4.z*k1.z + q4.w*k1.w;
            float d2 = q4.x*k2.x + q4.y*k2.y + q4.z*k2.z + q4.w*k2.w;
            float d3 = q4.x*k3.x + q4.y*k3.y + q4.z*k3.z + q4.w*k3.w;
#pragma unroll
            for (int o = 16; o > 0; o >>= 1) {
                d0 += __shfl_xor_sync(0xffffffffu, d0, o);
                d1 += __shfl_xor_sync(0xffffffffu, d1, o);
                d2 += __shfl_xor_sync(0xffffffffu, d2, o);
                d3 += __shfl_xor_sync(0xffffffffu, d3, o);
            }
            if (lane == 0) {
                sc[s]      = d0 * scale; sc[s + 4]  = d1 * scale;
                sc[s + 8]  = d2 * scale; sc[s + 12] = d3 * scale;
            }
            k0 = n0; k1 = n1; k2 = n2; k3 = n3;
        }
    }
    __syncthreads();

    // ---- softmax ----
    float m = -3.4e38f;
#pragma unroll
    for (int i = tid; i < KVLEN; i += 128) m = fmaxf(m, sc[i]);
#pragma unroll
    for (int o = 16; o > 0; o >>= 1)
        m = fmaxf(m, __shfl_xor_sync(0xffffffffu, m, o));
    if (lane == 0) wredA[warp] = m;
    __syncthreads();
    float bm = fmaxf(fmaxf(wredA[0], wredA[1]), fmaxf(wredA[2], wredA[3]));

    float ssum = 0.f;
#pragma unroll
    for (int i = tid; i < KVLEN; i += 128) {
        float e = __expf(sc[i] - bm);
        sc[i] = e;
        ssum += e;
    }
#pragma unroll
    for (int o = 16; o > 0; o >>= 1)
        ssum += __shfl_xor_sync(0xffffffffu, ssum, o);
    if (lane == 0) wredB[warp] = ssum;
    __syncthreads();
    const float inv = 1.0f / (wredB[0] + wredB[1] + wredB[2] + wredB[3]);

    // ---- pass 2: P @ V, 4 rows per warp-iter, pipelined loads ----
    const float* vbase = kbase + HEADS * DIM;
    const float4 vn4 = ((const float4*)vs)[lane];
    float4 acc = make_float4(0.f, 0.f, 0.f, 0.f);
    {
        float4 v0 = __ldcs((const float4*)(vbase + (size_t)(warp)      * rowstride) + lane);
        float4 v1 = __ldcs((const float4*)(vbase + (size_t)(warp + 4)  * rowstride) + lane);
        float4 v2 = __ldcs((const float4*)(vbase + (size_t)(warp + 8)  * rowstride) + lane);
        float4 v3 = __ldcs((const float4*)(vbase + (size_t)(warp + 12) * rowstride) + lane);
        for (int s = warp; s < KVLEN; s += 16) {
            float4 n0, n1, n2, n3;
            int sn = s + 16;
            if (sn < KVLEN) {
                n0 = __ldcs((const float4*)(vbase + (size_t)sn        * rowstride) + lane);
                n1 = __ldcs((const float4*)(vbase + (size_t)(sn + 4)  * rowstride) + lane);
                n2 = __ldcs((const float4*)(vbase + (size_t)(sn + 8)  * rowstride) + lane);
                n3 = __ldcs((const float4*)(vbase + (size_t)(sn + 12) * rowstride) + lane);
            }
            if (s      == p) v0 = vn4;
            if (s + 4  == p) v1 = vn4;
            if (s + 8  == p) v2 = vn4;
            if (s + 12 == p) v3 = vn4;
            float p0 = sc[s], p1 = sc[s + 4], p2 = sc[s + 8], p3 = sc[s + 12];
            acc.x += p0*v0.x + p1*v1.x + p2*v2.x + p3*v3.x;
            acc.y += p0*v0.y + p1*v1.y + p2*v2.y + p3*v3.y;
            acc.z += p0*v0.z + p1*v1.z + p2*v2.z + p3*v3.z;
            acc.w += p0*v0.w + p1*v1.w + p2*v2.w + p3*v3.w;
            v0 = n0; v1 = n1; v2 = n2; v3 = n3;
        }
    }
    ((float4*)(red + warp * DIM))[lane] = acc;
    __syncthreads();

    if (tid < DIM) {
        float o = red[tid] + red[DIM + tid] + red[2 * DIM + tid] + red[3 * DIM + tid];
        g_attn[(size_t)b * HID + h * DIM + tid] = o * inv;
    }
}

extern "C" void kernel_launch(void* const* d_in, const int* in_sizes, int n_in,
                              void* d_out, int out_size) {
    const float* hidden = (const float*)d_in[0];
    const float* cosb   = (const float*)d_in[1];
    const float* sinb   = (const float*)d_in[2];
    const float* cache  = (const float*)d_in[3];
    const int*   idx    = (const int*)d_in[4];
    const float* w_qkv  = (const float*)d_in[5];
    const float* w_o    = (const float*)d_in[6];
    float* out = (float*)d_out;

    float *attn_p, *part_p;
    cudaGetSymbolAddress((void**)&attn_p, g_attn);
    cudaGetSymbolAddress((void**)&part_p, g_part);

    // 1) QKV projection: 16 splits x chunk 256 (partials only; reduce fused into attn)
    gemm_splitk<256><<<dim3(NQKV / 256, QKV_SPLITS), 256>>>(hidden, w_qkv, part_p, NQKV, HID);
    // 2) attention: fused split-reduce + RoPE prologue, then KV streaming
    attn_kernel<<<BATCH * HEADS, 128>>>(part_p, cache, idx, cosb, sinb);
    // 3) output projection: 64 splits x chunk 64 + reduce
    gemm_splitk<64><<<dim3(HID / 256, OPJ_SPLITS), 256>>>(attn_p, w_o, part_p, HID, HID);
    reduce_splitk<<<(BATCH * HID + 255) / 256, 256>>>(part_p, out, HID, OPJ_SPLITS);
}